// round 13
// baseline (speedup 1.0000x reference)
#include <cuda_runtime.h>

#define T_STEPS 512
#define BATCH   256
#define NSTAGES 144     // q: s1 0..15, s2 16..79, s3 80..143

// Ping-pong activation buffers, layout [t][feature(16)][batch]
__device__ __align__(16) float g_act[2][T_STEPS * 16 * BATCH];
// Flags [stage][split(2)][t]; cleared by pre_kernel each replay.
__device__ unsigned g_flags[NSTAGES * 2 * T_STEPS];

#define FLAG(q, s) (g_flags + ((size_t)(q) * 2 + (s)) * T_STEPS)

// ---------------------------------------------------------------------------
__device__ __forceinline__ unsigned ld_acq(const unsigned* p) {
    unsigned v;
    asm volatile("ld.acquire.gpu.global.u32 %0, [%1];" : "=r"(v) : "l"(p) : "memory");
    return v;
}
__device__ __forceinline__ void st_rel(unsigned* p, unsigned v) {
    asm volatile("st.release.gpu.global.u32 [%0], %1;" :: "l"(p), "r"(v) : "memory");
}
__device__ __forceinline__ float2 ffma2(float2 a, float2 b, float2 c) {
    float2 d;
    asm("fma.rn.f32x2 %0, %1, %2, %3;"
        : "=l"(reinterpret_cast<unsigned long long&>(d))
        : "l"(reinterpret_cast<unsigned long long&>(a)),
          "l"(reinterpret_cast<unsigned long long&>(b)),
          "l"(reinterpret_cast<unsigned long long&>(c)));
    return d;
}
__device__ __forceinline__ void wg_bar(int id, int nthr) {
    asm volatile("bar.sync %0, %1;" :: "r"(id), "r"(nthr) : "memory");
}
__device__ __forceinline__ float tanh_fast(float x) {
    float y;
    asm("tanh.approx.f32 %0, %1;" : "=f"(y) : "f"(x));
    return y;
}
// LSTM nonlinearity via tanh.approx: 5 MUFU + ~8 FMA per value.
__device__ __forceinline__ float cell_one(float gi, float gf, float gg, float go,
                                          float& c) {
    float si = fmaf(tanh_fast(0.5f * gi), 0.5f, 0.5f);
    float sf = fmaf(tanh_fast(0.5f * gf), 0.5f, 0.5f);
    float tg = tanh_fast(gg);
    float so = fmaf(tanh_fast(0.5f * go), 0.5f, 0.5f);
    c = fmaf(sf, c, si * tg);
    return so * tanh_fast(c);
}

// ---------------------------------------------------------------------------
// Gate-packed weight fill: W4[k*H + j] = {w_i, w_f, w_g, w_o} for (k, j).
// ---------------------------------------------------------------------------
template<int H, int DIN0>
__device__ void fill_s4(float4* W4, float4* B4,
                        const float* Wih0, const float* Whh0,
                        const float* bih0, const float* bhh0,
                        const float* Wih,  const float* Whh,
                        const float* bih,  const float* bhh,
                        int l, int wtid, int stride) {
    constexpr int G = 4 * H, KM = 2 * H;
    const float* wi = l ? Wih + (size_t)(l - 1) * G * H : Wih0;
    const float* wh = l ? Whh + (size_t)(l - 1) * G * H : Whh0;
    const float* bi = l ? bih + (l - 1) * G : bih0;
    const float* bh = l ? bhh + (l - 1) * G : bhh0;
    const int din = l ? H : DIN0;
    for (int i = wtid; i < KM * H; i += stride) {
        int k = i / H, j = i % H;
        float v[4];
#pragma unroll
        for (int g = 0; g < 4; g++) {
            float w = 0.f;
            if (k < din)     w = wi[(g * H + j) * din + k];
            else if (k >= H) w = wh[(g * H + j) * H + (k - H)];
            v[g] = w;
        }
        W4[i] = make_float4(v[0], v[1], v[2], v[3]);
    }
    for (int jj = wtid; jj < H; jj += stride)
        B4[jj] = make_float4(bi[0 * H + jj] + bh[0 * H + jj],
                             bi[1 * H + jj] + bh[1 * H + jj],
                             bi[2 * H + jj] + bh[2 * H + jj],
                             bi[3 * H + jj] + bh[3 * H + jj]);
}

// ---------------------------------------------------------------------------
// Stage loop, JB j-blocking, NB in {1,2} batch-pairs per thread.
// Thread (jj, group): j in [jj*JB, jj*JB+JB), batch pairs group*NB..+NB-1.
// rows: [0,H) x rows (rows [DSTAGE,H) stay zero), pack-p h at [(p+1)H,(p+2)H).
// Per step: early flag probe -> P1 recurrent FMA -> (spin if needed) ->
// x LDG/commit -> bar -> P3 x FMA + act + h/gout write -> [pack1] -> end bar
// -> release.
// ---------------------------------------------------------------------------
template<int H, int JB, int PACK, int BPC_, int DSTAGE, int NTHR, bool FIRST, bool RELU, bool LAST>
__device__ void stage_loop(const float4* __restrict__ sW, const float4* __restrict__ sB,
                           float2* rows,
                           const float* __restrict__ bufin, float* __restrict__ bufout,
                           const unsigned* fin, unsigned* fout, int b0,
                           int wtid, int barid) {
    constexpr int NJJ = H / JB;
    constexpr int GROUPS = NTHR / NJJ;
    constexpr int NB = BPC_ / GROUPS;            // 1 or 2
    static_assert(NB == 1 || NB == 2, "NB must be 1 or 2");
    constexpr int KM = 2 * H;
    constexpr int QROW = BPC_ / 2;               // float4 slots per feature row
    constexpr int NQ = DSTAGE * QROW;
    constexpr int NLD = (NQ + NTHR - 1) / NTHR;
    const int jj = wtid / GROUPS, group = wtid % GROUPS;

    float2 c[PACK][JB][NB];
#pragma unroll
    for (int p = 0; p < PACK; p++)
#pragma unroll
        for (int jb = 0; jb < JB; jb++)
#pragma unroll
            for (int n = 0; n < NB; n++) c[p][jb][n] = make_float2(0.f, 0.f);

    for (int i = wtid; i < (PACK + 1) * H * BPC_; i += NTHR)
        rows[i] = make_float2(0.f, 0.f);
    wg_bar(barid, NTHR);

    for (int t = 0; t < T_STEPS; t++) {
        // --- early probe: hide acquire latency under P1 ---
        unsigned rdy = 1;
        if (!FIRST) rdy = ld_acq(fin + t);

        // --- P1: pack0 recurrent half ---
        float2 acc[4][JB][NB];
#pragma unroll
        for (int jb = 0; jb < JB; jb++) {
            float4 bv = sB[jj * JB + jb];
#pragma unroll
            for (int n = 0; n < NB; n++) {
                acc[0][jb][n] = make_float2(bv.x, bv.x);
                acc[1][jb][n] = make_float2(bv.y, bv.y);
                acc[2][jb][n] = make_float2(bv.z, bv.z);
                acc[3][jb][n] = make_float2(bv.w, bv.w);
            }
        }
#pragma unroll 4
        for (int k = H; k < KM; k++) {
            float2 v[NB];
            if (NB == 2) {
                float4 vv = *reinterpret_cast<const float4*>(&rows[k * BPC_ + 2 * group]);
                v[0] = make_float2(vv.x, vv.y);
                v[NB - 1] = make_float2(vv.z, vv.w);
            } else {
                v[0] = rows[k * BPC_ + group];
            }
#pragma unroll
            for (int jb = 0; jb < JB; jb++) {
                float4 wv = sW[k * H + jj * JB + jb];
                float2 w0 = make_float2(wv.x, wv.x), w1 = make_float2(wv.y, wv.y);
                float2 w2 = make_float2(wv.z, wv.z), w3 = make_float2(wv.w, wv.w);
#pragma unroll
                for (int n = 0; n < NB; n++) {
                    acc[0][jb][n] = ffma2(w0, v[n], acc[0][jb][n]);
                    acc[1][jb][n] = ffma2(w1, v[n], acc[1][jb][n]);
                    acc[2][jb][n] = ffma2(w2, v[n], acc[2][jb][n]);
                    acc[3][jb][n] = ffma2(w3, v[n], acc[3][jb][n]);
                }
            }
        }

        // --- spin only if probe missed ---
        if (!FIRST && !rdy) { const unsigned* f = fin + t; while (ld_acq(f) == 0) { } }

        // --- x loads + commit ---
        const float* bin = bufin + (size_t)t * 16 * BATCH + b0;
        float4 pf[NLD];
#pragma unroll
        for (int L = 0; L < NLD; L++) {
            int i = wtid + L * NTHR;
            if (NQ % NTHR == 0 || i < NQ) {
                int m = i / QROW, q4 = i % QROW;
                pf[L] = __ldcg(reinterpret_cast<const float4*>(&bin[m * BATCH + 4 * q4]));
            }
        }
#pragma unroll
        for (int L = 0; L < NLD; L++) {
            int i = wtid + L * NTHR;
            if (NQ % NTHR == 0 || i < NQ) {
                int m = i / QROW, q4 = i % QROW;
                float4 v = pf[L];
                if (RELU) {
                    v.x = fmaxf(v.x, 0.f); v.y = fmaxf(v.y, 0.f);
                    v.z = fmaxf(v.z, 0.f); v.w = fmaxf(v.w, 0.f);
                }
                *reinterpret_cast<float4*>(&rows[m * BPC_ + 2 * q4]) = v;
            }
        }
        wg_bar(barid, NTHR);   // x(t) visible; all P1 h-reads complete

        // --- P3: pack0 x half ---
#pragma unroll 4
        for (int k = 0; k < DSTAGE; k++) {
            float2 v[NB];
            if (NB == 2) {
                float4 vv = *reinterpret_cast<const float4*>(&rows[k * BPC_ + 2 * group]);
                v[0] = make_float2(vv.x, vv.y);
                v[NB - 1] = make_float2(vv.z, vv.w);
            } else {
                v[0] = rows[k * BPC_ + group];
            }
#pragma unroll
            for (int jb = 0; jb < JB; jb++) {
                float4 wv = sW[k * H + jj * JB + jb];
                float2 w0 = make_float2(wv.x, wv.x), w1 = make_float2(wv.y, wv.y);
                float2 w2 = make_float2(wv.z, wv.z), w3 = make_float2(wv.w, wv.w);
#pragma unroll
                for (int n = 0; n < NB; n++) {
                    acc[0][jb][n] = ffma2(w0, v[n], acc[0][jb][n]);
                    acc[1][jb][n] = ffma2(w1, v[n], acc[1][jb][n]);
                    acc[2][jb][n] = ffma2(w2, v[n], acc[2][jb][n]);
                    acc[3][jb][n] = ffma2(w3, v[n], acc[3][jb][n]);
                }
            }
        }
        // --- pack0 activations + h0 write ---
        float* bout = bufout + (size_t)t * 16 * BATCH + b0;
#pragma unroll
        for (int jb = 0; jb < JB; jb++) {
            int j = jj * JB + jb;
            float2 h[NB];
#pragma unroll
            for (int n = 0; n < NB; n++) {
                h[n].x = cell_one(acc[0][jb][n].x, acc[1][jb][n].x, acc[2][jb][n].x,
                                  acc[3][jb][n].x, c[0][jb][n].x);
                h[n].y = cell_one(acc[0][jb][n].y, acc[1][jb][n].y, acc[2][jb][n].y,
                                  acc[3][jb][n].y, c[0][jb][n].y);
            }
            if (NB == 2) {
                float4 hv = make_float4(h[0].x, h[0].y, h[NB - 1].x, h[NB - 1].y);
                *reinterpret_cast<float4*>(&rows[H * BPC_ + j * BPC_ + 2 * group]) = hv;
                if (PACK == 1)
                    *reinterpret_cast<float4*>(&bout[j * BATCH + 4 * group]) = hv;
            } else {
                rows[H * BPC_ + j * BPC_ + group] = h[0];
                if (PACK == 1)
                    *reinterpret_cast<float2*>(&bout[j * BATCH + 2 * group]) = h[0];
            }
        }

        if (PACK > 1) {
            wg_bar(barid, NTHR);   // h0(t) visible
            float2 acc1[4][JB][NB];
#pragma unroll
            for (int jb = 0; jb < JB; jb++) {
                float4 bv = sB[H + jj * JB + jb];
#pragma unroll
                for (int n = 0; n < NB; n++) {
                    acc1[0][jb][n] = make_float2(bv.x, bv.x);
                    acc1[1][jb][n] = make_float2(bv.y, bv.y);
                    acc1[2][jb][n] = make_float2(bv.z, bv.z);
                    acc1[3][jb][n] = make_float2(bv.w, bv.w);
                }
            }
#pragma unroll 4
            for (int k = 0; k < KM; k++) {
                float2 v[NB];
                if (NB == 2) {
                    float4 vv = *reinterpret_cast<const float4*>(&rows[(H + k) * BPC_ + 2 * group]);
                    v[0] = make_float2(vv.x, vv.y);
                    v[NB - 1] = make_float2(vv.z, vv.w);
                } else {
                    v[0] = rows[(H + k) * BPC_ + group];
                }
#pragma unroll
                for (int jb = 0; jb < JB; jb++) {
                    float4 wv = sW[KM * H + k * H + jj * JB + jb];
                    float2 w0 = make_float2(wv.x, wv.x), w1 = make_float2(wv.y, wv.y);
                    float2 w2 = make_float2(wv.z, wv.z), w3 = make_float2(wv.w, wv.w);
#pragma unroll
                    for (int n = 0; n < NB; n++) {
                        acc1[0][jb][n] = ffma2(w0, v[n], acc1[0][jb][n]);
                        acc1[1][jb][n] = ffma2(w1, v[n], acc1[1][jb][n]);
                        acc1[2][jb][n] = ffma2(w2, v[n], acc1[2][jb][n]);
                        acc1[3][jb][n] = ffma2(w3, v[n], acc1[3][jb][n]);
                    }
                }
            }
            float2 h[JB][NB];
#pragma unroll
            for (int jb = 0; jb < JB; jb++)
#pragma unroll
                for (int n = 0; n < NB; n++) {
                    h[jb][n].x = cell_one(acc1[0][jb][n].x, acc1[1][jb][n].x, acc1[2][jb][n].x,
                                          acc1[3][jb][n].x, c[1][jb][n].x);
                    h[jb][n].y = cell_one(acc1[0][jb][n].y, acc1[1][jb][n].y, acc1[2][jb][n].y,
                                          acc1[3][jb][n].y, c[1][jb][n].y);
                }
            wg_bar(barid, NTHR);   // all pack1 reads done
#pragma unroll
            for (int jb = 0; jb < JB; jb++) {
                int j = jj * JB + jb;
                if (NB == 2) {
                    float4 hv = make_float4(h[jb][0].x, h[jb][0].y, h[jb][NB - 1].x, h[jb][NB - 1].y);
                    *reinterpret_cast<float4*>(&rows[2 * H * BPC_ + j * BPC_ + 2 * group]) = hv;
                    *reinterpret_cast<float4*>(&bout[j * BATCH + 4 * group]) = hv;
                } else {
                    rows[2 * H * BPC_ + j * BPC_ + group] = h[jb][0];
                    *reinterpret_cast<float2*>(&bout[j * BATCH + 2 * group]) = h[jb][0];
                }
            }
        }

        wg_bar(barid, NTHR);   // h(t) + gout visible
        if (!LAST && wtid == 0) st_rel(fout + t, 1u);
    }
}

// ---------------------------------------------------------------------------
// 144 CTAs x 640 threads, one per SM:
//  CTA 0..127:  tid<512 (16 warps): s3 layer cta>>1, half cta&1 (JB=2, NB=1)
//               tid>=512 (4 warps): s2 layer cta>>1, half cta&1 (JB=2, NB=2)
//  CTA 128..143: tid<256: s1 pack2 unit cta-128, full batch (JB=1); else exit
// ---------------------------------------------------------------------------
__global__ void __launch_bounds__(640, 1)
lstm_pipe(const float* l1_Wih0, const float* l1_Whh0, const float* l1_bih0, const float* l1_bhh0,
          const float* l1_Wih,  const float* l1_Whh,  const float* l1_bih,  const float* l1_bhh,
          const float* l2_Wih0, const float* l2_Whh0, const float* l2_bih0, const float* l2_bhh0,
          const float* l2_Wih,  const float* l2_Whh,  const float* l2_bih,  const float* l2_bhh,
          const float* l3_Wih0, const float* l3_Whh0, const float* l3_bih0, const float* l3_bhh0,
          const float* l3_Wih,  const float* l3_Whh,  const float* l3_bih,  const float* l3_bhh)
{
    __shared__ __align__(16) float4 sW0[32 * 16];        // 8KB  s3 weights
    __shared__ __align__(16) float4 sB0[16];
    __shared__ __align__(16) float2 rows0[2 * 16 * 64];  // 16KB s3 rows
    __shared__ __align__(16) float4 sW1[128];            // 2KB  s2 / s1-pack2
    __shared__ __align__(16) float4 sB1[16];
    __shared__ __align__(16) float2 rows1[1536];         // 12KB (s2 uses 8KB)

    const int tid = threadIdx.x, cta = blockIdx.x;

    if (cta < 128) {
        const int d = cta >> 1;
        if (tid < 512) {
            fill_s4<16, 8>(sW0, sB0, l3_Wih0, l3_Whh0, l3_bih0, l3_bhh0,
                           l3_Wih, l3_Whh, l3_bih, l3_bhh, d, tid, 512);
        } else {
            fill_s4<8, 4>(sW1, sB1, l2_Wih0, l2_Whh0, l2_bih0, l2_bhh0,
                          l2_Wih, l2_Whh, l2_bih, l2_bhh, d, tid - 512, 128);
        }
    } else if (tid < 256) {
        const int i0 = cta - 128;
        fill_s4<4, 2>(sW1, sB1, l1_Wih0, l1_Whh0, l1_bih0, l1_bhh0,
                      l1_Wih, l1_Whh, l1_bih, l1_bhh, 2 * i0, tid, 256);
        fill_s4<4, 2>(sW1 + 32, sB1 + 4, l1_Wih0, l1_Whh0, l1_bih0, l1_bhh0,
                      l1_Wih, l1_Whh, l1_bih, l1_bhh, 2 * i0 + 1, tid, 256);
    }
    __syncthreads();

    if (cta < 128) {
        const int d = cta >> 1, s = cta & 1;
        const int b0 = s * 128;
        if (tid < 512) {
            // ---- s3 half-batch, 512 threads, JB=2 NB=1, barid 1 ----
            const int q = 80 + d;
            const float* bufin = g_act[q & 1];
            float* bufout = g_act[(q + 1) & 1];
            const unsigned* fin = (d == 0) ? FLAG(79, s) : FLAG(q - 1, s);
            unsigned* fout = FLAG(q, s);
            if (d == 0)
                stage_loop<16, 2, 1, 64, 8, 512, false, true, false>(sW0, sB0, rows0, bufin, bufout, fin, fout, b0, tid, 1);
            else if (d == 63)
                stage_loop<16, 2, 1, 64, 16, 512, false, false, true>(sW0, sB0, rows0, bufin, bufout, fin, fout, b0, tid, 1);
            else
                stage_loop<16, 2, 1, 64, 16, 512, false, false, false>(sW0, sB0, rows0, bufin, bufout, fin, fout, b0, tid, 1);
        } else {
            // ---- s2 half-batch, 128 threads, JB=2 NB=2, barid 2 ----
            const int wtid = tid - 512;
            const int q = 16 + d;
            const float* bufin = g_act[q & 1];
            float* bufout = g_act[(q + 1) & 1];
            const unsigned* fin = (d == 0) ? FLAG(15, 0) : FLAG(q - 1, s);
            unsigned* fout = FLAG(q, s);
            if (d == 0)
                stage_loop<8, 2, 1, 64, 4, 128, false, true, false>(sW1, sB1, rows1, bufin, bufout, fin, fout, b0, wtid, 2);
            else
                stage_loop<8, 2, 1, 64, 8, 128, false, false, false>(sW1, sB1, rows1, bufin, bufout, fin, fout, b0, wtid, 2);
        }
    } else if (tid < 256) {
        // ---- s1 pack2, full batch, 256 threads, JB=1 NB=2, barid 1 ----
        const int i0 = cta - 128, q = i0;
        const float* bufin = g_act[q & 1];
        float* bufout = g_act[(q + 1) & 1];
        const unsigned* fin = FLAG(q > 0 ? q - 1 : 0, 0);
        unsigned* fout = FLAG(q, 0);
        if (i0 == 0)
            stage_loop<4, 1, 2, 128, 2, 256, true, false, false>(sW1, sB1, rows1, bufin, bufout, fin, fout, 0, tid, 1);
        else
            stage_loop<4, 1, 2, 128, 4, 256, false, false, false>(sW1, sB1, rows1, bufin, bufout, fin, fout, 0, tid, 1);
    }
}

// ---------------------------------------------------------------------------
// Pre: transpose x -> g_act[0][t][m][b] AND clear all flags (replay-safe).
// Post: ReLU + FC(16->4).
// ---------------------------------------------------------------------------
__global__ void pre_kernel(const float* __restrict__ x) {
    int t = blockIdx.x, b = threadIdx.x;
    float2 v = *reinterpret_cast<const float2*>(&x[((size_t)t * BATCH + b) * 2]);
    g_act[0][(t * 16 + 0) * BATCH + b] = v.x;
    g_act[0][(t * 16 + 1) * BATCH + b] = v.y;
    int idx = t * BATCH + b;
    for (int i = idx; i < NSTAGES * 2 * T_STEPS; i += T_STEPS * BATCH)
        g_flags[i] = 0;
}

__global__ void fc_kernel(const float* __restrict__ fcW, const float* __restrict__ fcb,
                          float* __restrict__ out) {
    int t = blockIdx.x, b = threadIdx.x;
    float v[16];
#pragma unroll
    for (int m = 0; m < 16; m++)
        v[m] = fmaxf(g_act[0][(t * 16 + m) * BATCH + b], 0.f);
#pragma unroll
    for (int q = 0; q < 4; q++) {
        float a = fcb[q];
#pragma unroll
        for (int m = 0; m < 16; m++) a = fmaf(v[m], fcW[q * 16 + m], a);
        out[((size_t)t * BATCH + b) * 4 + q] = a;
    }
}

// ---------------------------------------------------------------------------
extern "C" void kernel_launch(void* const* d_in, const int* in_sizes, int n_in,
                              void* d_out, int out_size) {
#define F(i) ((const float*)d_in[i])
    pre_kernel<<<T_STEPS, BATCH>>>(F(0));
    lstm_pipe<<<144, 640>>>(
        F(1), F(2), F(3), F(4), F(5), F(6), F(7), F(8),
        F(9), F(10), F(11), F(12), F(13), F(14), F(15), F(16),
        F(17), F(18), F(19), F(20), F(21), F(22), F(23), F(24));
    fc_kernel<<<T_STEPS, BATCH>>>(F(25), F(26), (float*)d_out);
#undef F
}

// round 14
// speedup vs baseline: 1.0716x; 1.0716x over previous
#include <cuda_runtime.h>

#define T_STEPS 512
#define BATCH   256
#define NSTAGES 144     // q: s1 0..15, s2 16..79, s3 80..143

// Ping-pong activation buffers, layout [t][feature(16)][batch]
__device__ __align__(16) float g_act[2][T_STEPS * 16 * BATCH];
// Flags [stage][split(2)][t]; cleared by pre_kernel each replay.
__device__ unsigned g_flags[NSTAGES * 2 * T_STEPS];

#define FLAG(q, s) (g_flags + ((size_t)(q) * 2 + (s)) * T_STEPS)

// ---------------------------------------------------------------------------
__device__ __forceinline__ unsigned ld_acq(const unsigned* p) {
    unsigned v;
    asm volatile("ld.acquire.gpu.global.u32 %0, [%1];" : "=r"(v) : "l"(p) : "memory");
    return v;
}
__device__ __forceinline__ void st_rel(unsigned* p, unsigned v) {
    asm volatile("st.release.gpu.global.u32 [%0], %1;" :: "l"(p), "r"(v) : "memory");
}
__device__ __forceinline__ float2 ffma2(float2 a, float2 b, float2 c) {
    float2 d;
    asm("fma.rn.f32x2 %0, %1, %2, %3;"
        : "=l"(reinterpret_cast<unsigned long long&>(d))
        : "l"(reinterpret_cast<unsigned long long&>(a)),
          "l"(reinterpret_cast<unsigned long long&>(b)),
          "l"(reinterpret_cast<unsigned long long&>(c)));
    return d;
}
__device__ __forceinline__ void wg_bar(int id, int nthr) {
    asm volatile("bar.sync %0, %1;" :: "r"(id), "r"(nthr) : "memory");
}
__device__ __forceinline__ float tanh_fast(float x) {
    float y;
    asm("tanh.approx.f32 %0, %1;" : "=f"(y) : "f"(x));
    return y;
}
// LSTM nonlinearity via tanh.approx: 5 MUFU + ~8 FMA per value.
__device__ __forceinline__ float cell_one(float gi, float gf, float gg, float go,
                                          float& c) {
    float si = fmaf(tanh_fast(0.5f * gi), 0.5f, 0.5f);
    float sf = fmaf(tanh_fast(0.5f * gf), 0.5f, 0.5f);
    float tg = tanh_fast(gg);
    float so = fmaf(tanh_fast(0.5f * go), 0.5f, 0.5f);
    c = fmaf(sf, c, si * tg);
    return so * tanh_fast(c);
}

// ---------------------------------------------------------------------------
// Gate-packed weight fill: W4[k*H + j] = {w_i, w_f, w_g, w_o} for (k, j).
// ---------------------------------------------------------------------------
template<int H, int DIN0>
__device__ void fill_s4(float4* W4, float4* B4,
                        const float* Wih0, const float* Whh0,
                        const float* bih0, const float* bhh0,
                        const float* Wih,  const float* Whh,
                        const float* bih,  const float* bhh,
                        int l, int wtid, int stride) {
    constexpr int G = 4 * H, KM = 2 * H;
    const float* wi = l ? Wih + (size_t)(l - 1) * G * H : Wih0;
    const float* wh = l ? Whh + (size_t)(l - 1) * G * H : Whh0;
    const float* bi = l ? bih + (l - 1) * G : bih0;
    const float* bh = l ? bhh + (l - 1) * G : bhh0;
    const int din = l ? H : DIN0;
    for (int i = wtid; i < KM * H; i += stride) {
        int k = i / H, j = i % H;
        float v[4];
#pragma unroll
        for (int g = 0; g < 4; g++) {
            float w = 0.f;
            if (k < din)     w = wi[(g * H + j) * din + k];
            else if (k >= H) w = wh[(g * H + j) * H + (k - H)];
            v[g] = w;
        }
        W4[i] = make_float4(v[0], v[1], v[2], v[3]);
    }
    for (int jj = wtid; jj < H; jj += stride)
        B4[jj] = make_float4(bi[0 * H + jj] + bh[0 * H + jj],
                             bi[1 * H + jj] + bh[1 * H + jj],
                             bi[2 * H + jj] + bh[2 * H + jj],
                             bi[3 * H + jj] + bh[3 * H + jj]);
}

// ---------------------------------------------------------------------------
// Stage loop with JB=2 register blocking and NB=2 adjacent batch pairs
// (R11 configuration) + early flag probe hidden under P1.
// rows: [0,H) x rows (rows [DSTAGE,H) stay zero), pack-p h at [(p+1)H,(p+2)H).
// ---------------------------------------------------------------------------
template<int H, int JB, int PACK, int BPC_, int DSTAGE, int NTHR, bool FIRST, bool RELU, bool LAST>
__device__ void stage_loop(const float4* __restrict__ sW, const float4* __restrict__ sB,
                           float2* rows,
                           const float* __restrict__ bufin, float* __restrict__ bufout,
                           const unsigned* fin, unsigned* fout, int b0,
                           int wtid, int barid) {
    constexpr int NJJ = H / JB;
    constexpr int GROUPS = NTHR / NJJ;
    constexpr int NB = BPC_ / GROUPS;            // == 2 in all configs
    static_assert(NB == 2, "mapping assumes NB==2");
    constexpr int KM = 2 * H;
    constexpr int QROW = BPC_ / 2;               // float4 slots per feature row
    constexpr int NQ = DSTAGE * QROW;
    constexpr int NLD = (NQ + NTHR - 1) / NTHR;
    const int jj = wtid / GROUPS, group = wtid % GROUPS;

    float2 c[PACK][JB][NB];
#pragma unroll
    for (int p = 0; p < PACK; p++)
#pragma unroll
        for (int jb = 0; jb < JB; jb++)
#pragma unroll
            for (int n = 0; n < NB; n++) c[p][jb][n] = make_float2(0.f, 0.f);

    for (int i = wtid; i < (PACK + 1) * H * BPC_; i += NTHR)
        rows[i] = make_float2(0.f, 0.f);
    wg_bar(barid, NTHR);

    for (int t = 0; t < T_STEPS; t++) {
        // --- early probe: hide acquire latency under P1 ---
        unsigned rdy = 1;
        if (!FIRST) rdy = ld_acq(fin + t);

        // --- P1: pack0 recurrent half ---
        float2 acc[4][JB][NB];
#pragma unroll
        for (int jb = 0; jb < JB; jb++) {
            float4 bv = sB[jj * JB + jb];
#pragma unroll
            for (int n = 0; n < NB; n++) {
                acc[0][jb][n] = make_float2(bv.x, bv.x);
                acc[1][jb][n] = make_float2(bv.y, bv.y);
                acc[2][jb][n] = make_float2(bv.z, bv.z);
                acc[3][jb][n] = make_float2(bv.w, bv.w);
            }
        }
#pragma unroll 4
        for (int k = H; k < KM; k++) {
            float4 vv = *reinterpret_cast<const float4*>(&rows[k * BPC_ + 2 * group]);
            float2 v0 = make_float2(vv.x, vv.y), v1 = make_float2(vv.z, vv.w);
#pragma unroll
            for (int jb = 0; jb < JB; jb++) {
                float4 wv = sW[k * H + jj * JB + jb];
                float2 w0 = make_float2(wv.x, wv.x), w1 = make_float2(wv.y, wv.y);
                float2 w2 = make_float2(wv.z, wv.z), w3 = make_float2(wv.w, wv.w);
                acc[0][jb][0] = ffma2(w0, v0, acc[0][jb][0]);
                acc[1][jb][0] = ffma2(w1, v0, acc[1][jb][0]);
                acc[2][jb][0] = ffma2(w2, v0, acc[2][jb][0]);
                acc[3][jb][0] = ffma2(w3, v0, acc[3][jb][0]);
                acc[0][jb][1] = ffma2(w0, v1, acc[0][jb][1]);
                acc[1][jb][1] = ffma2(w1, v1, acc[1][jb][1]);
                acc[2][jb][1] = ffma2(w2, v1, acc[2][jb][1]);
                acc[3][jb][1] = ffma2(w3, v1, acc[3][jb][1]);
            }
        }

        // --- spin only if probe missed ---
        if (!FIRST && !rdy) { const unsigned* f = fin + t; while (ld_acq(f) == 0) { } }

        // --- x loads + commit ---
        const float* bin = bufin + (size_t)t * 16 * BATCH + b0;
        float4 pf[NLD];
#pragma unroll
        for (int L = 0; L < NLD; L++) {
            int i = wtid + L * NTHR;
            if (NQ % NTHR == 0 || i < NQ) {
                int m = i / QROW, q4 = i % QROW;
                pf[L] = __ldcg(reinterpret_cast<const float4*>(&bin[m * BATCH + 4 * q4]));
            }
        }
#pragma unroll
        for (int L = 0; L < NLD; L++) {
            int i = wtid + L * NTHR;
            if (NQ % NTHR == 0 || i < NQ) {
                int m = i / QROW, q4 = i % QROW;
                float4 v = pf[L];
                if (RELU) {
                    v.x = fmaxf(v.x, 0.f); v.y = fmaxf(v.y, 0.f);
                    v.z = fmaxf(v.z, 0.f); v.w = fmaxf(v.w, 0.f);
                }
                *reinterpret_cast<float4*>(&rows[m * BPC_ + 2 * q4]) = v;
            }
        }
        wg_bar(barid, NTHR);   // x(t) visible; all P1 h-reads complete

        // --- P3: pack0 x half ---
#pragma unroll 4
        for (int k = 0; k < DSTAGE; k++) {
            float4 vv = *reinterpret_cast<const float4*>(&rows[k * BPC_ + 2 * group]);
            float2 v0 = make_float2(vv.x, vv.y), v1 = make_float2(vv.z, vv.w);
#pragma unroll
            for (int jb = 0; jb < JB; jb++) {
                float4 wv = sW[k * H + jj * JB + jb];
                float2 w0 = make_float2(wv.x, wv.x), w1 = make_float2(wv.y, wv.y);
                float2 w2 = make_float2(wv.z, wv.z), w3 = make_float2(wv.w, wv.w);
                acc[0][jb][0] = ffma2(w0, v0, acc[0][jb][0]);
                acc[1][jb][0] = ffma2(w1, v0, acc[1][jb][0]);
                acc[2][jb][0] = ffma2(w2, v0, acc[2][jb][0]);
                acc[3][jb][0] = ffma2(w3, v0, acc[3][jb][0]);
                acc[0][jb][1] = ffma2(w0, v1, acc[0][jb][1]);
                acc[1][jb][1] = ffma2(w1, v1, acc[1][jb][1]);
                acc[2][jb][1] = ffma2(w2, v1, acc[2][jb][1]);
                acc[3][jb][1] = ffma2(w3, v1, acc[3][jb][1]);
            }
        }
        // --- pack0 activations + h0 write ---
        float* bout = bufout + (size_t)t * 16 * BATCH + b0;
#pragma unroll
        for (int jb = 0; jb < JB; jb++) {
            float2 h0, h1;
            h0.x = cell_one(acc[0][jb][0].x, acc[1][jb][0].x, acc[2][jb][0].x,
                            acc[3][jb][0].x, c[0][jb][0].x);
            h0.y = cell_one(acc[0][jb][0].y, acc[1][jb][0].y, acc[2][jb][0].y,
                            acc[3][jb][0].y, c[0][jb][0].y);
            h1.x = cell_one(acc[0][jb][1].x, acc[1][jb][1].x, acc[2][jb][1].x,
                            acc[3][jb][1].x, c[0][jb][1].x);
            h1.y = cell_one(acc[0][jb][1].y, acc[1][jb][1].y, acc[2][jb][1].y,
                            acc[3][jb][1].y, c[0][jb][1].y);
            int j = jj * JB + jb;
            float4 hv = make_float4(h0.x, h0.y, h1.x, h1.y);
            *reinterpret_cast<float4*>(&rows[H * BPC_ + j * BPC_ + 2 * group]) = hv;
            if (PACK == 1)
                *reinterpret_cast<float4*>(&bout[j * BATCH + 4 * group]) = hv;
        }

        if (PACK > 1) {
            wg_bar(barid, NTHR);   // h0(t) visible
            float2 acc1[4][JB][NB];
#pragma unroll
            for (int jb = 0; jb < JB; jb++) {
                float4 bv = sB[H + jj * JB + jb];
#pragma unroll
                for (int n = 0; n < NB; n++) {
                    acc1[0][jb][n] = make_float2(bv.x, bv.x);
                    acc1[1][jb][n] = make_float2(bv.y, bv.y);
                    acc1[2][jb][n] = make_float2(bv.z, bv.z);
                    acc1[3][jb][n] = make_float2(bv.w, bv.w);
                }
            }
#pragma unroll 4
            for (int k = 0; k < KM; k++) {
                float4 vv = *reinterpret_cast<const float4*>(&rows[(H + k) * BPC_ + 2 * group]);
                float2 v0 = make_float2(vv.x, vv.y), v1 = make_float2(vv.z, vv.w);
#pragma unroll
                for (int jb = 0; jb < JB; jb++) {
                    float4 wv = sW[KM * H + k * H + jj * JB + jb];
                    float2 w0 = make_float2(wv.x, wv.x), w1 = make_float2(wv.y, wv.y);
                    float2 w2 = make_float2(wv.z, wv.z), w3 = make_float2(wv.w, wv.w);
                    acc1[0][jb][0] = ffma2(w0, v0, acc1[0][jb][0]);
                    acc1[1][jb][0] = ffma2(w1, v0, acc1[1][jb][0]);
                    acc1[2][jb][0] = ffma2(w2, v0, acc1[2][jb][0]);
                    acc1[3][jb][0] = ffma2(w3, v0, acc1[3][jb][0]);
                    acc1[0][jb][1] = ffma2(w0, v1, acc1[0][jb][1]);
                    acc1[1][jb][1] = ffma2(w1, v1, acc1[1][jb][1]);
                    acc1[2][jb][1] = ffma2(w2, v1, acc1[2][jb][1]);
                    acc1[3][jb][1] = ffma2(w3, v1, acc1[3][jb][1]);
                }
            }
            float4 hv[JB];
#pragma unroll
            for (int jb = 0; jb < JB; jb++) {
                float2 h0, h1;
                h0.x = cell_one(acc1[0][jb][0].x, acc1[1][jb][0].x, acc1[2][jb][0].x,
                                acc1[3][jb][0].x, c[1][jb][0].x);
                h0.y = cell_one(acc1[0][jb][0].y, acc1[1][jb][0].y, acc1[2][jb][0].y,
                                acc1[3][jb][0].y, c[1][jb][0].y);
                h1.x = cell_one(acc1[0][jb][1].x, acc1[1][jb][1].x, acc1[2][jb][1].x,
                                acc1[3][jb][1].x, c[1][jb][1].x);
                h1.y = cell_one(acc1[0][jb][1].y, acc1[1][jb][1].y, acc1[2][jb][1].y,
                                acc1[3][jb][1].y, c[1][jb][1].y);
                hv[jb] = make_float4(h0.x, h0.y, h1.x, h1.y);
            }
            wg_bar(barid, NTHR);   // all pack1 reads done
#pragma unroll
            for (int jb = 0; jb < JB; jb++) {
                int j = jj * JB + jb;
                *reinterpret_cast<float4*>(&rows[2 * H * BPC_ + j * BPC_ + 2 * group]) = hv[jb];
                *reinterpret_cast<float4*>(&bout[j * BATCH + 4 * group]) = hv[jb];
            }
        }

        wg_bar(barid, NTHR);   // h(t) + gout visible
        if (!LAST && wtid == 0) st_rel(fout + t, 1u);
    }
}

// ---------------------------------------------------------------------------
// 144 CTAs x 384 threads, one per SM:
//  CTA 0..127:  tid<256: s3 layer cta>>1, batch half cta&1 (BPC=64, JB=2)
//               tid>=256: s2 layer cta>>1, batch half cta&1 (BPC=64, JB=2)
//  CTA 128..143: tid<256: s1 pack2 unit cta-128, full batch (JB=1); else exit
// ---------------------------------------------------------------------------
__global__ void __launch_bounds__(384, 1)
lstm_pipe(const float* l1_Wih0, const float* l1_Whh0, const float* l1_bih0, const float* l1_bhh0,
          const float* l1_Wih,  const float* l1_Whh,  const float* l1_bih,  const float* l1_bhh,
          const float* l2_Wih0, const float* l2_Whh0, const float* l2_bih0, const float* l2_bhh0,
          const float* l2_Wih,  const float* l2_Whh,  const float* l2_bih,  const float* l2_bhh,
          const float* l3_Wih0, const float* l3_Whh0, const float* l3_bih0, const float* l3_bhh0,
          const float* l3_Wih,  const float* l3_Whh,  const float* l3_bih,  const float* l3_bhh)
{
    __shared__ __align__(16) float4 sW0[32 * 16];        // 8KB  s3 weights
    __shared__ __align__(16) float4 sB0[16];
    __shared__ __align__(16) float2 rows0[2 * 16 * 64];  // 16KB s3 rows
    __shared__ __align__(16) float4 sW1[128];            // 2KB  s2 / s1-pack2
    __shared__ __align__(16) float4 sB1[16];
    __shared__ __align__(16) float2 rows1[2048];         // 16KB

    const int tid = threadIdx.x, cta = blockIdx.x;

    if (cta < 128) {
        const int d = cta >> 1;
        if (tid < 256) {
            fill_s4<16, 8>(sW0, sB0, l3_Wih0, l3_Whh0, l3_bih0, l3_bhh0,
                           l3_Wih, l3_Whh, l3_bih, l3_bhh, d, tid, 256);
        } else {
            fill_s4<8, 4>(sW1, sB1, l2_Wih0, l2_Whh0, l2_bih0, l2_bhh0,
                          l2_Wih, l2_Whh, l2_bih, l2_bhh, d, tid - 256, 128);
        }
    } else if (tid < 256) {
        const int i0 = cta - 128;
        fill_s4<4, 2>(sW1, sB1, l1_Wih0, l1_Whh0, l1_bih0, l1_bhh0,
                      l1_Wih, l1_Whh, l1_bih, l1_bhh, 2 * i0, tid, 256);
        fill_s4<4, 2>(sW1 + 32, sB1 + 4, l1_Wih0, l1_Whh0, l1_bih0, l1_bhh0,
                      l1_Wih, l1_Whh, l1_bih, l1_bhh, 2 * i0 + 1, tid, 256);
    }
    __syncthreads();

    if (cta < 128) {
        const int d = cta >> 1, s = cta & 1;
        const int b0 = s * 128;
        if (tid < 256) {
            // ---- s3 half-batch, 256 threads, JB=2 NB=2, barid 1 ----
            const int q = 80 + d;
            const float* bufin = g_act[q & 1];
            float* bufout = g_act[(q + 1) & 1];
            const unsigned* fin = (d == 0) ? FLAG(79, s) : FLAG(q - 1, s);
            unsigned* fout = FLAG(q, s);
            if (d == 0)
                stage_loop<16, 2, 1, 64, 8, 256, false, true, false>(sW0, sB0, rows0, bufin, bufout, fin, fout, b0, tid, 1);
            else if (d == 63)
                stage_loop<16, 2, 1, 64, 16, 256, false, false, true>(sW0, sB0, rows0, bufin, bufout, fin, fout, b0, tid, 1);
            else
                stage_loop<16, 2, 1, 64, 16, 256, false, false, false>(sW0, sB0, rows0, bufin, bufout, fin, fout, b0, tid, 1);
        } else {
            // ---- s2 half-batch, 128 threads, JB=2 NB=2, barid 2 ----
            const int wtid = tid - 256;
            const int q = 16 + d;
            const float* bufin = g_act[q & 1];
            float* bufout = g_act[(q + 1) & 1];
            const unsigned* fin = (d == 0) ? FLAG(15, 0) : FLAG(q - 1, s);
            unsigned* fout = FLAG(q, s);
            if (d == 0)
                stage_loop<8, 2, 1, 64, 4, 128, false, true, false>(sW1, sB1, rows1, bufin, bufout, fin, fout, b0, wtid, 2);
            else
                stage_loop<8, 2, 1, 64, 8, 128, false, false, false>(sW1, sB1, rows1, bufin, bufout, fin, fout, b0, wtid, 2);
        }
    } else if (tid < 256) {
        // ---- s1 pack2, full batch, 256 threads, JB=1 NB=2, barid 1 ----
        const int i0 = cta - 128, q = i0;
        const float* bufin = g_act[q & 1];
        float* bufout = g_act[(q + 1) & 1];
        const unsigned* fin = FLAG(q > 0 ? q - 1 : 0, 0);
        unsigned* fout = FLAG(q, 0);
        if (i0 == 0)
            stage_loop<4, 1, 2, 128, 2, 256, true, false, false>(sW1, sB1, rows1, bufin, bufout, fin, fout, 0, tid, 1);
        else
            stage_loop<4, 1, 2, 128, 4, 256, false, false, false>(sW1, sB1, rows1, bufin, bufout, fin, fout, 0, tid, 1);
    }
}

// ---------------------------------------------------------------------------
// Pre: transpose x -> g_act[0][t][m][b] AND clear all flags (replay-safe).
// Post: ReLU + FC(16->4).
// ---------------------------------------------------------------------------
__global__ void pre_kernel(const float* __restrict__ x) {
    int t = blockIdx.x, b = threadIdx.x;
    float2 v = *reinterpret_cast<const float2*>(&x[((size_t)t * BATCH + b) * 2]);
    g_act[0][(t * 16 + 0) * BATCH + b] = v.x;
    g_act[0][(t * 16 + 1) * BATCH + b] = v.y;
    int idx = t * BATCH + b;
    for (int i = idx; i < NSTAGES * 2 * T_STEPS; i += T_STEPS * BATCH)
        g_flags[i] = 0;
}

__global__ void fc_kernel(const float* __restrict__ fcW, const float* __restrict__ fcb,
                          float* __restrict__ out) {
    int t = blockIdx.x, b = threadIdx.x;
    float v[16];
#pragma unroll
    for (int m = 0; m < 16; m++)
        v[m] = fmaxf(g_act[0][(t * 16 + m) * BATCH + b], 0.f);
#pragma unroll
    for (int q = 0; q < 4; q++) {
        float a = fcb[q];
#pragma unroll
        for (int m = 0; m < 16; m++) a = fmaf(v[m], fcW[q * 16 + m], a);
        out[((size_t)t * BATCH + b) * 4 + q] = a;
    }
}

// ---------------------------------------------------------------------------
extern "C" void kernel_launch(void* const* d_in, const int* in_sizes, int n_in,
                              void* d_out, int out_size) {
#define F(i) ((const float*)d_in[i])
    pre_kernel<<<T_STEPS, BATCH>>>(F(0));
    lstm_pipe<<<144, 384>>>(
        F(1), F(2), F(3), F(4), F(5), F(6), F(7), F(8),
        F(9), F(10), F(11), F(12), F(13), F(14), F(15), F(16),
        F(17), F(18), F(19), F(20), F(21), F(22), F(23), F(24));
    fc_kernel<<<T_STEPS, BATCH>>>(F(25), F(26), (float*)d_out);
#undef F
}

// round 15
// speedup vs baseline: 1.0891x; 1.0163x over previous
#include <cuda_runtime.h>

#define T_STEPS 512
#define BATCH   256
#define NSTAGES 136     // q: s1 0..7 (pack4), s2 8..71, s3 72..135

// Ping-pong activation buffers, layout [t][feature(16)][batch]
__device__ __align__(16) float g_act[2][T_STEPS * 16 * BATCH];
// Flags [stage][split(2)][t]; cleared by pre_kernel each replay.
__device__ unsigned g_flags[NSTAGES * 2 * T_STEPS];

#define FLAG(q, s) (g_flags + ((size_t)(q) * 2 + (s)) * T_STEPS)

// ---------------------------------------------------------------------------
__device__ __forceinline__ unsigned ld_acq(const unsigned* p) {
    unsigned v;
    asm volatile("ld.acquire.gpu.global.u32 %0, [%1];" : "=r"(v) : "l"(p) : "memory");
    return v;
}
__device__ __forceinline__ void st_rel(unsigned* p, unsigned v) {
    asm volatile("st.release.gpu.global.u32 [%0], %1;" :: "l"(p), "r"(v) : "memory");
}
__device__ __forceinline__ float2 ffma2(float2 a, float2 b, float2 c) {
    float2 d;
    asm("fma.rn.f32x2 %0, %1, %2, %3;"
        : "=l"(reinterpret_cast<unsigned long long&>(d))
        : "l"(reinterpret_cast<unsigned long long&>(a)),
          "l"(reinterpret_cast<unsigned long long&>(b)),
          "l"(reinterpret_cast<unsigned long long&>(c)));
    return d;
}
__device__ __forceinline__ void wg_bar(int id, int nthr) {
    asm volatile("bar.sync %0, %1;" :: "r"(id), "r"(nthr) : "memory");
}
__device__ __forceinline__ float tanh_fast(float x) {
    float y;
    asm("tanh.approx.f32 %0, %1;" : "=f"(y) : "f"(x));
    return y;
}
// LSTM nonlinearity via tanh.approx: 5 MUFU + ~8 FMA per value.
__device__ __forceinline__ float cell_one(float gi, float gf, float gg, float go,
                                          float& c) {
    float si = fmaf(tanh_fast(0.5f * gi), 0.5f, 0.5f);
    float sf = fmaf(tanh_fast(0.5f * gf), 0.5f, 0.5f);
    float tg = tanh_fast(gg);
    float so = fmaf(tanh_fast(0.5f * go), 0.5f, 0.5f);
    c = fmaf(sf, c, si * tg);
    return so * tanh_fast(c);
}

// ---------------------------------------------------------------------------
// Gate-packed weight fill: W4[k*H + j] = {w_i, w_f, w_g, w_o} for (k, j).
// ---------------------------------------------------------------------------
template<int H, int DIN0>
__device__ void fill_s4(float4* W4, float4* B4,
                        const float* Wih0, const float* Whh0,
                        const float* bih0, const float* bhh0,
                        const float* Wih,  const float* Whh,
                        const float* bih,  const float* bhh,
                        int l, int wtid, int stride) {
    constexpr int G = 4 * H, KM = 2 * H;
    const float* wi = l ? Wih + (size_t)(l - 1) * G * H : Wih0;
    const float* wh = l ? Whh + (size_t)(l - 1) * G * H : Whh0;
    const float* bi = l ? bih + (l - 1) * G : bih0;
    const float* bh = l ? bhh + (l - 1) * G : bhh0;
    const int din = l ? H : DIN0;
    for (int i = wtid; i < KM * H; i += stride) {
        int k = i / H, j = i % H;
        float v[4];
#pragma unroll
        for (int g = 0; g < 4; g++) {
            float w = 0.f;
            if (k < din)     w = wi[(g * H + j) * din + k];
            else if (k >= H) w = wh[(g * H + j) * H + (k - H)];
            v[g] = w;
        }
        W4[i] = make_float4(v[0], v[1], v[2], v[3]);
    }
    for (int jj = wtid; jj < H; jj += stride)
        B4[jj] = make_float4(bi[0 * H + jj] + bh[0 * H + jj],
                             bi[1 * H + jj] + bh[1 * H + jj],
                             bi[2 * H + jj] + bh[2 * H + jj],
                             bi[3 * H + jj] + bh[3 * H + jj]);
}

// ---------------------------------------------------------------------------
// Stage loop (R11 structure): JB j-blocking, NB=2 adjacent batch pairs,
// generalized pack loop.  rows: [0,H) x rows (rows [DSTAGE,H) stay zero),
// pack-p h(t-1) at [(p+1)H,(p+2)H).  Per step:
//   P1 pack0 recurrent FMA; poll; x LDG+commit; bar;
//   P3 pack0 x FMA + act + h0 write (+gout if PACK==1);
//   for p=1..PACK-1: bar; FMA(input=h_{p-1}(t), rec=h_p(t-1)) + act; bar;
//                    write h_p (+gout if last);
//   end bar; release.
// ---------------------------------------------------------------------------
template<int H, int JB, int PACK, int BPC_, int DSTAGE, int NTHR, bool FIRST, bool RELU, bool LAST>
__device__ void stage_loop(const float4* __restrict__ sW, const float4* __restrict__ sB,
                           float2* rows,
                           const float* __restrict__ bufin, float* __restrict__ bufout,
                           const unsigned* fin, unsigned* fout, int b0,
                           int wtid, int barid) {
    constexpr int NJJ = H / JB;
    constexpr int GROUPS = NTHR / NJJ;
    constexpr int NB = BPC_ / GROUPS;            // == 2 in all configs
    static_assert(NB == 2, "mapping assumes NB==2");
    constexpr int KM = 2 * H;
    constexpr int QROW = BPC_ / 2;               // float4 slots per feature row
    constexpr int NQ = DSTAGE * QROW;
    constexpr int NLD = (NQ + NTHR - 1) / NTHR;
    const int jj = wtid / GROUPS, group = wtid % GROUPS;

    float2 c[PACK][JB][NB];
#pragma unroll
    for (int p = 0; p < PACK; p++)
#pragma unroll
        for (int jb = 0; jb < JB; jb++)
#pragma unroll
            for (int n = 0; n < NB; n++) c[p][jb][n] = make_float2(0.f, 0.f);

    for (int i = wtid; i < (PACK + 1) * H * BPC_; i += NTHR)
        rows[i] = make_float2(0.f, 0.f);
    wg_bar(barid, NTHR);

    for (int t = 0; t < T_STEPS; t++) {
        // --- P1: pack0 recurrent half ---
        float2 acc[4][JB][NB];
#pragma unroll
        for (int jb = 0; jb < JB; jb++) {
            float4 bv = sB[jj * JB + jb];
#pragma unroll
            for (int n = 0; n < NB; n++) {
                acc[0][jb][n] = make_float2(bv.x, bv.x);
                acc[1][jb][n] = make_float2(bv.y, bv.y);
                acc[2][jb][n] = make_float2(bv.z, bv.z);
                acc[3][jb][n] = make_float2(bv.w, bv.w);
            }
        }
#pragma unroll 4
        for (int k = H; k < KM; k++) {
            float4 vv = *reinterpret_cast<const float4*>(&rows[k * BPC_ + 2 * group]);
            float2 v0 = make_float2(vv.x, vv.y), v1 = make_float2(vv.z, vv.w);
#pragma unroll
            for (int jb = 0; jb < JB; jb++) {
                float4 wv = sW[k * H + jj * JB + jb];
                float2 w0 = make_float2(wv.x, wv.x), w1 = make_float2(wv.y, wv.y);
                float2 w2 = make_float2(wv.z, wv.z), w3 = make_float2(wv.w, wv.w);
                acc[0][jb][0] = ffma2(w0, v0, acc[0][jb][0]);
                acc[1][jb][0] = ffma2(w1, v0, acc[1][jb][0]);
                acc[2][jb][0] = ffma2(w2, v0, acc[2][jb][0]);
                acc[3][jb][0] = ffma2(w3, v0, acc[3][jb][0]);
                acc[0][jb][1] = ffma2(w0, v1, acc[0][jb][1]);
                acc[1][jb][1] = ffma2(w1, v1, acc[1][jb][1]);
                acc[2][jb][1] = ffma2(w2, v1, acc[2][jb][1]);
                acc[3][jb][1] = ffma2(w3, v1, acc[3][jb][1]);
            }
        }

        // --- poll + x loads + commit ---
        if (!FIRST) { const unsigned* f = fin + t; while (ld_acq(f) == 0) { } }
        const float* bin = bufin + (size_t)t * 16 * BATCH + b0;
        float4 pf[NLD];
#pragma unroll
        for (int L = 0; L < NLD; L++) {
            int i = wtid + L * NTHR;
            if (NQ % NTHR == 0 || i < NQ) {
                int m = i / QROW, q4 = i % QROW;
                pf[L] = __ldcg(reinterpret_cast<const float4*>(&bin[m * BATCH + 4 * q4]));
            }
        }
#pragma unroll
        for (int L = 0; L < NLD; L++) {
            int i = wtid + L * NTHR;
            if (NQ % NTHR == 0 || i < NQ) {
                int m = i / QROW, q4 = i % QROW;
                float4 v = pf[L];
                if (RELU) {
                    v.x = fmaxf(v.x, 0.f); v.y = fmaxf(v.y, 0.f);
                    v.z = fmaxf(v.z, 0.f); v.w = fmaxf(v.w, 0.f);
                }
                *reinterpret_cast<float4*>(&rows[m * BPC_ + 2 * q4]) = v;
            }
        }
        wg_bar(barid, NTHR);   // x(t) visible; all P1 h-reads complete

        // --- P3: pack0 x half ---
#pragma unroll 4
        for (int k = 0; k < DSTAGE; k++) {
            float4 vv = *reinterpret_cast<const float4*>(&rows[k * BPC_ + 2 * group]);
            float2 v0 = make_float2(vv.x, vv.y), v1 = make_float2(vv.z, vv.w);
#pragma unroll
            for (int jb = 0; jb < JB; jb++) {
                float4 wv = sW[k * H + jj * JB + jb];
                float2 w0 = make_float2(wv.x, wv.x), w1 = make_float2(wv.y, wv.y);
                float2 w2 = make_float2(wv.z, wv.z), w3 = make_float2(wv.w, wv.w);
                acc[0][jb][0] = ffma2(w0, v0, acc[0][jb][0]);
                acc[1][jb][0] = ffma2(w1, v0, acc[1][jb][0]);
                acc[2][jb][0] = ffma2(w2, v0, acc[2][jb][0]);
                acc[3][jb][0] = ffma2(w3, v0, acc[3][jb][0]);
                acc[0][jb][1] = ffma2(w0, v1, acc[0][jb][1]);
                acc[1][jb][1] = ffma2(w1, v1, acc[1][jb][1]);
                acc[2][jb][1] = ffma2(w2, v1, acc[2][jb][1]);
                acc[3][jb][1] = ffma2(w3, v1, acc[3][jb][1]);
            }
        }
        // --- pack0 activations + h0 write ---
        float* bout = bufout + (size_t)t * 16 * BATCH + b0;
#pragma unroll
        for (int jb = 0; jb < JB; jb++) {
            float2 h0, h1;
            h0.x = cell_one(acc[0][jb][0].x, acc[1][jb][0].x, acc[2][jb][0].x,
                            acc[3][jb][0].x, c[0][jb][0].x);
            h0.y = cell_one(acc[0][jb][0].y, acc[1][jb][0].y, acc[2][jb][0].y,
                            acc[3][jb][0].y, c[0][jb][0].y);
            h1.x = cell_one(acc[0][jb][1].x, acc[1][jb][1].x, acc[2][jb][1].x,
                            acc[3][jb][1].x, c[0][jb][1].x);
            h1.y = cell_one(acc[0][jb][1].y, acc[1][jb][1].y, acc[2][jb][1].y,
                            acc[3][jb][1].y, c[0][jb][1].y);
            int j = jj * JB + jb;
            float4 hv = make_float4(h0.x, h0.y, h1.x, h1.y);
            *reinterpret_cast<float4*>(&rows[H * BPC_ + j * BPC_ + 2 * group]) = hv;
            if (PACK == 1)
                *reinterpret_cast<float4*>(&bout[j * BATCH + 4 * group]) = hv;
        }

        // --- packs 1..PACK-1 ---
#pragma unroll
        for (int p = 1; p < PACK; p++) {
            wg_bar(barid, NTHR);   // h_{p-1}(t) visible
            float2 acc1[4][JB][NB];
#pragma unroll
            for (int jb = 0; jb < JB; jb++) {
                float4 bv = sB[p * H + jj * JB + jb];
#pragma unroll
                for (int n = 0; n < NB; n++) {
                    acc1[0][jb][n] = make_float2(bv.x, bv.x);
                    acc1[1][jb][n] = make_float2(bv.y, bv.y);
                    acc1[2][jb][n] = make_float2(bv.z, bv.z);
                    acc1[3][jb][n] = make_float2(bv.w, bv.w);
                }
            }
#pragma unroll 4
            for (int k = 0; k < KM; k++) {
                float4 vv = *reinterpret_cast<const float4*>(&rows[(p * H + k) * BPC_ + 2 * group]);
                float2 v0 = make_float2(vv.x, vv.y), v1 = make_float2(vv.z, vv.w);
#pragma unroll
                for (int jb = 0; jb < JB; jb++) {
                    float4 wv = sW[p * KM * H + k * H + jj * JB + jb];
                    float2 w0 = make_float2(wv.x, wv.x), w1 = make_float2(wv.y, wv.y);
                    float2 w2 = make_float2(wv.z, wv.z), w3 = make_float2(wv.w, wv.w);
                    acc1[0][jb][0] = ffma2(w0, v0, acc1[0][jb][0]);
                    acc1[1][jb][0] = ffma2(w1, v0, acc1[1][jb][0]);
                    acc1[2][jb][0] = ffma2(w2, v0, acc1[2][jb][0]);
                    acc1[3][jb][0] = ffma2(w3, v0, acc1[3][jb][0]);
                    acc1[0][jb][1] = ffma2(w0, v1, acc1[0][jb][1]);
                    acc1[1][jb][1] = ffma2(w1, v1, acc1[1][jb][1]);
                    acc1[2][jb][1] = ffma2(w2, v1, acc1[2][jb][1]);
                    acc1[3][jb][1] = ffma2(w3, v1, acc1[3][jb][1]);
                }
            }
            float4 hv[JB];
#pragma unroll
            for (int jb = 0; jb < JB; jb++) {
                float2 h0, h1;
                h0.x = cell_one(acc1[0][jb][0].x, acc1[1][jb][0].x, acc1[2][jb][0].x,
                                acc1[3][jb][0].x, c[p][jb][0].x);
                h0.y = cell_one(acc1[0][jb][0].y, acc1[1][jb][0].y, acc1[2][jb][0].y,
                                acc1[3][jb][0].y, c[p][jb][0].y);
                h1.x = cell_one(acc1[0][jb][1].x, acc1[1][jb][1].x, acc1[2][jb][1].x,
                                acc1[3][jb][1].x, c[p][jb][1].x);
                h1.y = cell_one(acc1[0][jb][1].y, acc1[1][jb][1].y, acc1[2][jb][1].y,
                                acc1[3][jb][1].y, c[p][jb][1].y);
                hv[jb] = make_float4(h0.x, h0.y, h1.x, h1.y);
            }
            wg_bar(barid, NTHR);   // all pack-p reads done
#pragma unroll
            for (int jb = 0; jb < JB; jb++) {
                int j = jj * JB + jb;
                *reinterpret_cast<float4*>(&rows[(p + 1) * H * BPC_ + j * BPC_ + 2 * group]) = hv[jb];
                if (p == PACK - 1)
                    *reinterpret_cast<float4*>(&bout[j * BATCH + 4 * group]) = hv[jb];
            }
        }

        wg_bar(barid, NTHR);   // h(t) + gout visible
        if (!LAST && wtid == 0) st_rel(fout + t, 1u);
    }
}

// ---------------------------------------------------------------------------
// 136 CTAs x 384 threads, one per SM:
//  CTA 0..127:  tid<256: s3 layer cta>>1, batch half cta&1 (BPC=64, JB=2)
//               tid>=256: s2 layer cta>>1, batch half cta&1 (BPC=64, JB=2)
//  CTA 128..135: tid<256: s1 pack4 unit cta-128, full batch (JB=1); else exit
// ---------------------------------------------------------------------------
__global__ void __launch_bounds__(384, 1)
lstm_pipe(const float* l1_Wih0, const float* l1_Whh0, const float* l1_bih0, const float* l1_bhh0,
          const float* l1_Wih,  const float* l1_Whh,  const float* l1_bih,  const float* l1_bhh,
          const float* l2_Wih0, const float* l2_Whh0, const float* l2_bih0, const float* l2_bhh0,
          const float* l2_Wih,  const float* l2_Whh,  const float* l2_bih,  const float* l2_bhh,
          const float* l3_Wih0, const float* l3_Whh0, const float* l3_bih0, const float* l3_bhh0,
          const float* l3_Wih,  const float* l3_Whh,  const float* l3_bih,  const float* l3_bhh)
{
    __shared__ __align__(16) float4 sW0[32 * 16];        // 8KB  s3 weights
    __shared__ __align__(16) float4 sB0[16];
    __shared__ __align__(16) float2 rows0[2 * 16 * 64];  // 16KB s3 rows
    __shared__ __align__(16) float4 sW1[128];            // 2KB  s2 / s1-pack4
    __shared__ __align__(16) float4 sB1[16];
    __shared__ __align__(16) float2 rows1[2560];         // 20KB (s1 pack4 needs 5*4*128)

    const int tid = threadIdx.x, cta = blockIdx.x;

    if (cta < 128) {
        const int d = cta >> 1;
        if (tid < 256) {
            fill_s4<16, 8>(sW0, sB0, l3_Wih0, l3_Whh0, l3_bih0, l3_bhh0,
                           l3_Wih, l3_Whh, l3_bih, l3_bhh, d, tid, 256);
        } else {
            fill_s4<8, 4>(sW1, sB1, l2_Wih0, l2_Whh0, l2_bih0, l2_bhh0,
                          l2_Wih, l2_Whh, l2_bih, l2_bhh, d, tid - 256, 128);
        }
    } else if (tid < 256) {
        const int i0 = cta - 128;
#pragma unroll
        for (int p = 0; p < 4; p++)
            fill_s4<4, 2>(sW1 + p * 32, sB1 + p * 4,
                          l1_Wih0, l1_Whh0, l1_bih0, l1_bhh0,
                          l1_Wih, l1_Whh, l1_bih, l1_bhh, 4 * i0 + p, tid, 256);
    }
    __syncthreads();

    if (cta < 128) {
        const int d = cta >> 1, s = cta & 1;
        const int b0 = s * 128;
        if (tid < 256) {
            // ---- s3 half-batch, 256 threads, JB=2 NB=2, barid 1 ----
            const int q = 72 + d;
            const float* bufin = g_act[q & 1];
            float* bufout = g_act[(q + 1) & 1];
            const unsigned* fin = (d == 0) ? FLAG(71, s) : FLAG(q - 1, s);
            unsigned* fout = FLAG(q, s);
            if (d == 0)
                stage_loop<16, 2, 1, 64, 8, 256, false, true, false>(sW0, sB0, rows0, bufin, bufout, fin, fout, b0, tid, 1);
            else if (d == 63)
                stage_loop<16, 2, 1, 64, 16, 256, false, false, true>(sW0, sB0, rows0, bufin, bufout, fin, fout, b0, tid, 1);
            else
                stage_loop<16, 2, 1, 64, 16, 256, false, false, false>(sW0, sB0, rows0, bufin, bufout, fin, fout, b0, tid, 1);
        } else {
            // ---- s2 half-batch, 128 threads, JB=2 NB=2, barid 2 ----
            const int wtid = tid - 256;
            const int q = 8 + d;
            const float* bufin = g_act[q & 1];
            float* bufout = g_act[(q + 1) & 1];
            const unsigned* fin = (d == 0) ? FLAG(7, 0) : FLAG(q - 1, s);
            unsigned* fout = FLAG(q, s);
            if (d == 0)
                stage_loop<8, 2, 1, 64, 4, 128, false, true, false>(sW1, sB1, rows1, bufin, bufout, fin, fout, b0, wtid, 2);
            else
                stage_loop<8, 2, 1, 64, 8, 128, false, false, false>(sW1, sB1, rows1, bufin, bufout, fin, fout, b0, wtid, 2);
        }
    } else if (tid < 256) {
        // ---- s1 pack4, full batch, 256 threads, JB=1 NB=2, barid 1 ----
        const int i0 = cta - 128, q = i0;
        const float* bufin = g_act[q & 1];
        float* bufout = g_act[(q + 1) & 1];
        const unsigned* fin = FLAG(q > 0 ? q - 1 : 0, 0);
        unsigned* fout = FLAG(q, 0);
        if (i0 == 0)
            stage_loop<4, 1, 4, 128, 2, 256, true, false, false>(sW1, sB1, rows1, bufin, bufout, fin, fout, 0, tid, 1);
        else
            stage_loop<4, 1, 4, 128, 4, 256, false, false, false>(sW1, sB1, rows1, bufin, bufout, fin, fout, 0, tid, 1);
    }
}

// ---------------------------------------------------------------------------
// Pre: transpose x -> g_act[0][t][m][b] AND clear all flags (replay-safe).
// Post: ReLU + FC(16->4).
// ---------------------------------------------------------------------------
__global__ void pre_kernel(const float* __restrict__ x) {
    int t = blockIdx.x, b = threadIdx.x;
    float2 v = *reinterpret_cast<const float2*>(&x[((size_t)t * BATCH + b) * 2]);
    g_act[0][(t * 16 + 0) * BATCH + b] = v.x;
    g_act[0][(t * 16 + 1) * BATCH + b] = v.y;
    int idx = t * BATCH + b;
    for (int i = idx; i < NSTAGES * 2 * T_STEPS; i += T_STEPS * BATCH)
        g_flags[i] = 0;
}

__global__ void fc_kernel(const float* __restrict__ fcW, const float* __restrict__ fcb,
                          float* __restrict__ out) {
    int t = blockIdx.x, b = threadIdx.x;
    float v[16];
#pragma unroll
    for (int m = 0; m < 16; m++)
        v[m] = fmaxf(g_act[0][(t * 16 + m) * BATCH + b], 0.f);
#pragma unroll
    for (int q = 0; q < 4; q++) {
        float a = fcb[q];
#pragma unroll
        for (int m = 0; m < 16; m++) a = fmaf(v[m], fcW[q * 16 + m], a);
        out[((size_t)t * BATCH + b) * 4 + q] = a;
    }
}

// ---------------------------------------------------------------------------
extern "C" void kernel_launch(void* const* d_in, const int* in_sizes, int n_in,
                              void* d_out, int out_size) {
#define F(i) ((const float*)d_in[i])
    pre_kernel<<<T_STEPS, BATCH>>>(F(0));
    lstm_pipe<<<136, 384>>>(
        F(1), F(2), F(3), F(4), F(5), F(6), F(7), F(8),
        F(9), F(10), F(11), F(12), F(13), F(14), F(15), F(16),
        F(17), F(18), F(19), F(20), F(21), F(22), F(23), F(24));
    fc_kernel<<<T_STEPS, BATCH>>>(F(25), F(26), (float*)d_out);
#undef F
}

// round 16
// speedup vs baseline: 1.1237x; 1.0318x over previous
#include <cuda_runtime.h>

#define T_STEPS 512
#define BATCH   256
#define NSTAGES 136     // q: s1 0..7 (pack4), s2 8..71, s3 72..135

// Ping-pong activation buffers, layout [t][feature(16)][batch]
__device__ __align__(16) float g_act[2][T_STEPS * 16 * BATCH];
// Flags [stage][split(4)][t]; cleared by pre_kernel each replay.
__device__ unsigned g_flags[NSTAGES * 4 * T_STEPS];

#define FLAG(q, s) (g_flags + ((size_t)(q) * 4 + (s)) * T_STEPS)

// ---------------------------------------------------------------------------
__device__ __forceinline__ unsigned ld_acq(const unsigned* p) {
    unsigned v;
    asm volatile("ld.acquire.gpu.global.u32 %0, [%1];" : "=r"(v) : "l"(p) : "memory");
    return v;
}
__device__ __forceinline__ void st_rel(unsigned* p, unsigned v) {
    asm volatile("st.release.gpu.global.u32 [%0], %1;" :: "l"(p), "r"(v) : "memory");
}
__device__ __forceinline__ float2 ffma2(float2 a, float2 b, float2 c) {
    float2 d;
    asm("fma.rn.f32x2 %0, %1, %2, %3;"
        : "=l"(reinterpret_cast<unsigned long long&>(d))
        : "l"(reinterpret_cast<unsigned long long&>(a)),
          "l"(reinterpret_cast<unsigned long long&>(b)),
          "l"(reinterpret_cast<unsigned long long&>(c)));
    return d;
}
__device__ __forceinline__ void wg_bar(int id, int nthr) {
    asm volatile("bar.sync %0, %1;" :: "r"(id), "r"(nthr) : "memory");
}
__device__ __forceinline__ float tanh_fast(float x) {
    float y;
    asm("tanh.approx.f32 %0, %1;" : "=f"(y) : "f"(x));
    return y;
}
// LSTM nonlinearity via tanh.approx: 5 MUFU + ~8 FMA per value.
__device__ __forceinline__ float cell_one(float gi, float gf, float gg, float go,
                                          float& c) {
    float si = fmaf(tanh_fast(0.5f * gi), 0.5f, 0.5f);
    float sf = fmaf(tanh_fast(0.5f * gf), 0.5f, 0.5f);
    float tg = tanh_fast(gg);
    float so = fmaf(tanh_fast(0.5f * go), 0.5f, 0.5f);
    c = fmaf(sf, c, si * tg);
    return so * tanh_fast(c);
}

// ---------------------------------------------------------------------------
// Gate-packed weight fill: W4[k*H + j] = {w_i, w_f, w_g, w_o} for (k, j).
// ---------------------------------------------------------------------------
template<int H, int DIN0>
__device__ void fill_s4(float4* W4, float4* B4,
                        const float* Wih0, const float* Whh0,
                        const float* bih0, const float* bhh0,
                        const float* Wih,  const float* Whh,
                        const float* bih,  const float* bhh,
                        int l, int wtid, int stride) {
    constexpr int G = 4 * H, KM = 2 * H;
    const float* wi = l ? Wih + (size_t)(l - 1) * G * H : Wih0;
    const float* wh = l ? Whh + (size_t)(l - 1) * G * H : Whh0;
    const float* bi = l ? bih + (l - 1) * G : bih0;
    const float* bh = l ? bhh + (l - 1) * G : bhh0;
    const int din = l ? H : DIN0;
    for (int i = wtid; i < KM * H; i += stride) {
        int k = i / H, j = i % H;
        float v[4];
#pragma unroll
        for (int g = 0; g < 4; g++) {
            float w = 0.f;
            if (k < din)     w = wi[(g * H + j) * din + k];
            else if (k >= H) w = wh[(g * H + j) * H + (k - H)];
            v[g] = w;
        }
        W4[i] = make_float4(v[0], v[1], v[2], v[3]);
    }
    for (int jj = wtid; jj < H; jj += stride)
        B4[jj] = make_float4(bi[0 * H + jj] + bh[0 * H + jj],
                             bi[1 * H + jj] + bh[1 * H + jj],
                             bi[2 * H + jj] + bh[2 * H + jj],
                             bi[3 * H + jj] + bh[3 * H + jj]);
}

// ---------------------------------------------------------------------------
// Stage loop: JB j-blocking, NB=2 adjacent batch pairs, generalized pack loop.
// rows: [0,H) x rows (rows [DSTAGE,H) stay zero), pack-p h(t-1) at
// [(p+1)H,(p+2)H).  Per step:
//   P1 pack0 recurrent FMA; poll flag(t); x LDG+commit; bar;
//   P3 pack0 x FMA + act + h0 write (+gout if PACK==1);
//   for p=1..PACK-1: bar; FMA + act; bar; write h_p (+gout if last);
//   end bar; release.
// ---------------------------------------------------------------------------
template<int H, int JB, int PACK, int BPC_, int DSTAGE, int NTHR, bool FIRST, bool RELU, bool LAST>
__device__ void stage_loop(const float4* __restrict__ sW, const float4* __restrict__ sB,
                           float2* rows,
                           const float* __restrict__ bufin, float* __restrict__ bufout,
                           const unsigned* fin, unsigned* fout, int b0,
                           int wtid, int barid) {
    constexpr int NJJ = H / JB;
    constexpr int GROUPS = NTHR / NJJ;
    constexpr int NB = BPC_ / GROUPS;            // == 2 in all configs
    static_assert(NB == 2, "mapping assumes NB==2");
    constexpr int KM = 2 * H;
    constexpr int QROW = BPC_ / 2;               // float4 slots per feature row
    constexpr int NQ = DSTAGE * QROW;
    constexpr int NLD = (NQ + NTHR - 1) / NTHR;
    const int jj = wtid / GROUPS, group = wtid % GROUPS;

    float2 c[PACK][JB][NB];
#pragma unroll
    for (int p = 0; p < PACK; p++)
#pragma unroll
        for (int jb = 0; jb < JB; jb++)
#pragma unroll
            for (int n = 0; n < NB; n++) c[p][jb][n] = make_float2(0.f, 0.f);

    for (int i = wtid; i < (PACK + 1) * H * BPC_; i += NTHR)
        rows[i] = make_float2(0.f, 0.f);
    wg_bar(barid, NTHR);

    for (int t = 0; t < T_STEPS; t++) {
        // --- P1: pack0 recurrent half ---
        float2 acc[4][JB][NB];
#pragma unroll
        for (int jb = 0; jb < JB; jb++) {
            float4 bv = sB[jj * JB + jb];
#pragma unroll
            for (int n = 0; n < NB; n++) {
                acc[0][jb][n] = make_float2(bv.x, bv.x);
                acc[1][jb][n] = make_float2(bv.y, bv.y);
                acc[2][jb][n] = make_float2(bv.z, bv.z);
                acc[3][jb][n] = make_float2(bv.w, bv.w);
            }
        }
#pragma unroll 4
        for (int k = H; k < KM; k++) {
            float4 vv = *reinterpret_cast<const float4*>(&rows[k * BPC_ + 2 * group]);
            float2 v0 = make_float2(vv.x, vv.y), v1 = make_float2(vv.z, vv.w);
#pragma unroll
            for (int jb = 0; jb < JB; jb++) {
                float4 wv = sW[k * H + jj * JB + jb];
                float2 w0 = make_float2(wv.x, wv.x), w1 = make_float2(wv.y, wv.y);
                float2 w2 = make_float2(wv.z, wv.z), w3 = make_float2(wv.w, wv.w);
                acc[0][jb][0] = ffma2(w0, v0, acc[0][jb][0]);
                acc[1][jb][0] = ffma2(w1, v0, acc[1][jb][0]);
                acc[2][jb][0] = ffma2(w2, v0, acc[2][jb][0]);
                acc[3][jb][0] = ffma2(w3, v0, acc[3][jb][0]);
                acc[0][jb][1] = ffma2(w0, v1, acc[0][jb][1]);
                acc[1][jb][1] = ffma2(w1, v1, acc[1][jb][1]);
                acc[2][jb][1] = ffma2(w2, v1, acc[2][jb][1]);
                acc[3][jb][1] = ffma2(w3, v1, acc[3][jb][1]);
            }
        }

        // --- poll + x loads + commit ---
        if (!FIRST) { const unsigned* f = fin + t; while (ld_acq(f) == 0) { } }
        const float* bin = bufin + (size_t)t * 16 * BATCH + b0;
        float4 pf[NLD];
#pragma unroll
        for (int L = 0; L < NLD; L++) {
            int i = wtid + L * NTHR;
            if (NQ % NTHR == 0 || i < NQ) {
                int m = i / QROW, q4 = i % QROW;
                pf[L] = __ldcg(reinterpret_cast<const float4*>(&bin[m * BATCH + 4 * q4]));
            }
        }
#pragma unroll
        for (int L = 0; L < NLD; L++) {
            int i = wtid + L * NTHR;
            if (NQ % NTHR == 0 || i < NQ) {
                int m = i / QROW, q4 = i % QROW;
                float4 v = pf[L];
                if (RELU) {
                    v.x = fmaxf(v.x, 0.f); v.y = fmaxf(v.y, 0.f);
                    v.z = fmaxf(v.z, 0.f); v.w = fmaxf(v.w, 0.f);
                }
                *reinterpret_cast<float4*>(&rows[m * BPC_ + 2 * q4]) = v;
            }
        }
        wg_bar(barid, NTHR);   // x(t) visible; all P1 h-reads complete

        // --- P3: pack0 x half ---
#pragma unroll 4
        for (int k = 0; k < DSTAGE; k++) {
            float4 vv = *reinterpret_cast<const float4*>(&rows[k * BPC_ + 2 * group]);
            float2 v0 = make_float2(vv.x, vv.y), v1 = make_float2(vv.z, vv.w);
#pragma unroll
            for (int jb = 0; jb < JB; jb++) {
                float4 wv = sW[k * H + jj * JB + jb];
                float2 w0 = make_float2(wv.x, wv.x), w1 = make_float2(wv.y, wv.y);
                float2 w2 = make_float2(wv.z, wv.z), w3 = make_float2(wv.w, wv.w);
                acc[0][jb][0] = ffma2(w0, v0, acc[0][jb][0]);
                acc[1][jb][0] = ffma2(w1, v0, acc[1][jb][0]);
                acc[2][jb][0] = ffma2(w2, v0, acc[2][jb][0]);
                acc[3][jb][0] = ffma2(w3, v0, acc[3][jb][0]);
                acc[0][jb][1] = ffma2(w0, v1, acc[0][jb][1]);
                acc[1][jb][1] = ffma2(w1, v1, acc[1][jb][1]);
                acc[2][jb][1] = ffma2(w2, v1, acc[2][jb][1]);
                acc[3][jb][1] = ffma2(w3, v1, acc[3][jb][1]);
            }
        }
        // --- pack0 activations + h0 write ---
        float* bout = bufout + (size_t)t * 16 * BATCH + b0;
#pragma unroll
        for (int jb = 0; jb < JB; jb++) {
            float2 h0, h1;
            h0.x = cell_one(acc[0][jb][0].x, acc[1][jb][0].x, acc[2][jb][0].x,
                            acc[3][jb][0].x, c[0][jb][0].x);
            h0.y = cell_one(acc[0][jb][0].y, acc[1][jb][0].y, acc[2][jb][0].y,
                            acc[3][jb][0].y, c[0][jb][0].y);
            h1.x = cell_one(acc[0][jb][1].x, acc[1][jb][1].x, acc[2][jb][1].x,
                            acc[3][jb][1].x, c[0][jb][1].x);
            h1.y = cell_one(acc[0][jb][1].y, acc[1][jb][1].y, acc[2][jb][1].y,
                            acc[3][jb][1].y, c[0][jb][1].y);
            int j = jj * JB + jb;
            float4 hv = make_float4(h0.x, h0.y, h1.x, h1.y);
            *reinterpret_cast<float4*>(&rows[H * BPC_ + j * BPC_ + 2 * group]) = hv;
            if (PACK == 1)
                *reinterpret_cast<float4*>(&bout[j * BATCH + 4 * group]) = hv;
        }

        // --- packs 1..PACK-1 ---
#pragma unroll
        for (int p = 1; p < PACK; p++) {
            wg_bar(barid, NTHR);   // h_{p-1}(t) visible
            float2 acc1[4][JB][NB];
#pragma unroll
            for (int jb = 0; jb < JB; jb++) {
                float4 bv = sB[p * H + jj * JB + jb];
#pragma unroll
                for (int n = 0; n < NB; n++) {
                    acc1[0][jb][n] = make_float2(bv.x, bv.x);
                    acc1[1][jb][n] = make_float2(bv.y, bv.y);
                    acc1[2][jb][n] = make_float2(bv.z, bv.z);
                    acc1[3][jb][n] = make_float2(bv.w, bv.w);
                }
            }
#pragma unroll 4
            for (int k = 0; k < KM; k++) {
                float4 vv = *reinterpret_cast<const float4*>(&rows[(p * H + k) * BPC_ + 2 * group]);
                float2 v0 = make_float2(vv.x, vv.y), v1 = make_float2(vv.z, vv.w);
#pragma unroll
                for (int jb = 0; jb < JB; jb++) {
                    float4 wv = sW[p * KM * H + k * H + jj * JB + jb];
                    float2 w0 = make_float2(wv.x, wv.x), w1 = make_float2(wv.y, wv.y);
                    float2 w2 = make_float2(wv.z, wv.z), w3 = make_float2(wv.w, wv.w);
                    acc1[0][jb][0] = ffma2(w0, v0, acc1[0][jb][0]);
                    acc1[1][jb][0] = ffma2(w1, v0, acc1[1][jb][0]);
                    acc1[2][jb][0] = ffma2(w2, v0, acc1[2][jb][0]);
                    acc1[3][jb][0] = ffma2(w3, v0, acc1[3][jb][0]);
                    acc1[0][jb][1] = ffma2(w0, v1, acc1[0][jb][1]);
                    acc1[1][jb][1] = ffma2(w1, v1, acc1[1][jb][1]);
                    acc1[2][jb][1] = ffma2(w2, v1, acc1[2][jb][1]);
                    acc1[3][jb][1] = ffma2(w3, v1, acc1[3][jb][1]);
                }
            }
            float4 hv[JB];
#pragma unroll
            for (int jb = 0; jb < JB; jb++) {
                float2 h0, h1;
                h0.x = cell_one(acc1[0][jb][0].x, acc1[1][jb][0].x, acc1[2][jb][0].x,
                                acc1[3][jb][0].x, c[p][jb][0].x);
                h0.y = cell_one(acc1[0][jb][0].y, acc1[1][jb][0].y, acc1[2][jb][0].y,
                                acc1[3][jb][0].y, c[p][jb][0].y);
                h1.x = cell_one(acc1[0][jb][1].x, acc1[1][jb][1].x, acc1[2][jb][1].x,
                                acc1[3][jb][1].x, c[p][jb][1].x);
                h1.y = cell_one(acc1[0][jb][1].y, acc1[1][jb][1].y, acc1[2][jb][1].y,
                                acc1[3][jb][1].y, c[p][jb][1].y);
                hv[jb] = make_float4(h0.x, h0.y, h1.x, h1.y);
            }
            wg_bar(barid, NTHR);   // all pack-p reads done
#pragma unroll
            for (int jb = 0; jb < JB; jb++) {
                int j = jj * JB + jb;
                *reinterpret_cast<float4*>(&rows[(p + 1) * H * BPC_ + j * BPC_ + 2 * group]) = hv[jb];
                if (p == PACK - 1)
                    *reinterpret_cast<float4*>(&bout[j * BATCH + 4 * group]) = hv[jb];
            }
        }

        wg_bar(barid, NTHR);   // h(t) + gout visible
        if (!LAST && wtid == 0) st_rel(fout + t, 1u);
    }
}

// ---------------------------------------------------------------------------
// 136 CTAs x 384 threads, one per SM:
//  CTA 0..127:  tid<128:      s3 layer cta>>1, quarter (cta&1)*2+0 (BPC=32)
//               tid in [128,256): s3 same layer, quarter (cta&1)*2+1
//               tid>=256:     s2 layer cta>>1, batch half cta&1 (BPC=64)
//  CTA 128..135: tid<256: s1 pack4 unit cta-128, full batch; else exit
// The two s3 quarter-groups run independent barriers/flags so their
// FMA/MUFU/LDS phases desynchronize and interleave on shared SMSPs.
// ---------------------------------------------------------------------------
__global__ void __launch_bounds__(384, 1)
lstm_pipe(const float* l1_Wih0, const float* l1_Whh0, const float* l1_bih0, const float* l1_bhh0,
          const float* l1_Wih,  const float* l1_Whh,  const float* l1_bih,  const float* l1_bhh,
          const float* l2_Wih0, const float* l2_Whh0, const float* l2_bih0, const float* l2_bhh0,
          const float* l2_Wih,  const float* l2_Whh,  const float* l2_bih,  const float* l2_bhh,
          const float* l3_Wih0, const float* l3_Whh0, const float* l3_bih0, const float* l3_bhh0,
          const float* l3_Wih,  const float* l3_Whh,  const float* l3_bih,  const float* l3_bhh)
{
    __shared__ __align__(16) float4 sW0[32 * 16];        // 8KB  s3 weights (shared)
    __shared__ __align__(16) float4 sB0[16];
    __shared__ __align__(16) float2 rows0a[2 * 16 * 32]; // 8KB  s3 quarter A
    __shared__ __align__(16) float2 rows0b[2 * 16 * 32]; // 8KB  s3 quarter B
    __shared__ __align__(16) float4 sW1[128];            // 2KB  s2 / s1-pack4
    __shared__ __align__(16) float4 sB1[16];
    __shared__ __align__(16) float2 rows1[2560];         // 20KB (s1 pack4 max)

    const int tid = threadIdx.x, cta = blockIdx.x;

    if (cta < 128) {
        const int d = cta >> 1;
        if (tid < 256) {
            fill_s4<16, 8>(sW0, sB0, l3_Wih0, l3_Whh0, l3_bih0, l3_bhh0,
                           l3_Wih, l3_Whh, l3_bih, l3_bhh, d, tid, 256);
        } else {
            fill_s4<8, 4>(sW1, sB1, l2_Wih0, l2_Whh0, l2_bih0, l2_bhh0,
                          l2_Wih, l2_Whh, l2_bih, l2_bhh, d, tid - 256, 128);
        }
    } else if (tid < 256) {
        const int i0 = cta - 128;
#pragma unroll
        for (int p = 0; p < 4; p++)
            fill_s4<4, 2>(sW1 + p * 32, sB1 + p * 4,
                          l1_Wih0, l1_Whh0, l1_bih0, l1_bhh0,
                          l1_Wih, l1_Whh, l1_bih, l1_bhh, 4 * i0 + p, tid, 256);
    }
    __syncthreads();

    if (cta < 128) {
        const int d = cta >> 1;
        if (tid < 256) {
            // ---- s3 quarter-batch, two independent 128-thread groups ----
            const int gi = tid >> 7;                  // 0 or 1
            const int wtid = tid & 127;
            const int ss = (cta & 1) * 2 + gi;        // quarter index 0..3
            const int q = 72 + d;
            const float* bufin = g_act[q & 1];
            float* bufout = g_act[(q + 1) & 1];
            const unsigned* fin = (d == 0) ? FLAG(71, ss >> 1) : FLAG(q - 1, ss);
            unsigned* fout = FLAG(q, ss);
            float2* rows = gi ? rows0b : rows0a;
            const int b0 = ss * 64;
            const int barid = 1 + gi * 2;             // 1 or 3 (s2 uses 2)
            if (d == 0)
                stage_loop<16, 2, 1, 32, 8, 128, false, true, false>(sW0, sB0, rows, bufin, bufout, fin, fout, b0, wtid, barid);
            else if (d == 63)
                stage_loop<16, 2, 1, 32, 16, 128, false, false, true>(sW0, sB0, rows, bufin, bufout, fin, fout, b0, wtid, barid);
            else
                stage_loop<16, 2, 1, 32, 16, 128, false, false, false>(sW0, sB0, rows, bufin, bufout, fin, fout, b0, wtid, barid);
        } else {
            // ---- s2 half-batch, 128 threads, JB=2 NB=2, barid 2 ----
            const int wtid = tid - 256;
            const int s = cta & 1;
            const int q = 8 + d;
            const float* bufin = g_act[q & 1];
            float* bufout = g_act[(q + 1) & 1];
            const unsigned* fin = (d == 0) ? FLAG(7, 0) : FLAG(q - 1, s);
            unsigned* fout = FLAG(q, s);
            const int b0 = s * 128;
            if (d == 0)
                stage_loop<8, 2, 1, 64, 4, 128, false, true, false>(sW1, sB1, rows1, bufin, bufout, fin, fout, b0, wtid, 2);
            else
                stage_loop<8, 2, 1, 64, 8, 128, false, false, false>(sW1, sB1, rows1, bufin, bufout, fin, fout, b0, wtid, 2);
        }
    } else if (tid < 256) {
        // ---- s1 pack4, full batch, 256 threads, JB=1 NB=2, barid 1 ----
        const int i0 = cta - 128, q = i0;
        const float* bufin = g_act[q & 1];
        float* bufout = g_act[(q + 1) & 1];
        const unsigned* fin = FLAG(q > 0 ? q - 1 : 0, 0);
        unsigned* fout = FLAG(q, 0);
        if (i0 == 0)
            stage_loop<4, 1, 4, 128, 2, 256, true, false, false>(sW1, sB1, rows1, bufin, bufout, fin, fout, 0, tid, 1);
        else
            stage_loop<4, 1, 4, 128, 4, 256, false, false, false>(sW1, sB1, rows1, bufin, bufout, fin, fout, 0, tid, 1);
    }
}

// ---------------------------------------------------------------------------
// Pre: transpose x -> g_act[0][t][m][b] AND clear all flags (replay-safe).
// Post: ReLU + FC(16->4).
// ---------------------------------------------------------------------------
__global__ void pre_kernel(const float* __restrict__ x) {
    int t = blockIdx.x, b = threadIdx.x;
    float2 v = *reinterpret_cast<const float2*>(&x[((size_t)t * BATCH + b) * 2]);
    g_act[0][(t * 16 + 0) * BATCH + b] = v.x;
    g_act[0][(t * 16 + 1) * BATCH + b] = v.y;
    int idx = t * BATCH + b;
    for (int i = idx; i < NSTAGES * 4 * T_STEPS; i += T_STEPS * BATCH)
        g_flags[i] = 0;
}

__global__ void fc_kernel(const float* __restrict__ fcW, const float* __restrict__ fcb,
                          float* __restrict__ out) {
    int t = blockIdx.x, b = threadIdx.x;
    float v[16];
#pragma unroll
    for (int m = 0; m < 16; m++)
        v[m] = fmaxf(g_act[0][(t * 16 + m) * BATCH + b], 0.f);
#pragma unroll
    for (int q = 0; q < 4; q++) {
        float a = fcb[q];
#pragma unroll
        for (int m = 0; m < 16; m++) a = fmaf(v[m], fcW[q * 16 + m], a);
        out[((size_t)t * BATCH + b) * 4 + q] = a;
    }
}

// ---------------------------------------------------------------------------
extern "C" void kernel_launch(void* const* d_in, const int* in_sizes, int n_in,
                              void* d_out, int out_size) {
#define F(i) ((const float*)d_in[i])
    pre_kernel<<<T_STEPS, BATCH>>>(F(0));
    lstm_pipe<<<136, 384>>>(
        F(1), F(2), F(3), F(4), F(5), F(6), F(7), F(8),
        F(9), F(10), F(11), F(12), F(13), F(14), F(15), F(16),
        F(17), F(18), F(19), F(20), F(21), F(22), F(23), F(24));
    fc_kernel<<<T_STEPS, BATCH>>>(F(25), F(26), (float*)d_out);
#undef F
}